// round 2
// baseline (speedup 1.0000x reference)
#include <cuda_runtime.h>
#include <cstdint>

#define VOCABN 50000
#define EMS    300
#define BB     32
#define QQ     16
#define DD     10
#define LL     1000
#define SPLIT  2
#define LCHUNK (LL / SPLIT)

__device__ float g_nq[BB * QQ];
__device__ float g_tw[BB * QQ];

__device__ __forceinline__ unsigned long long fma2(unsigned long long a,
                                                   unsigned long long b,
                                                   unsigned long long c) {
    unsigned long long d;
    asm("fma.rn.f32x2 %0, %1, %2, %3;" : "=l"(d) : "l"(a), "l"(b), "l"(c));
    return d;
}

__device__ __forceinline__ float lo_plus_hi(unsigned long long v) {
    float lo, hi;
    asm("mov.b64 {%0, %1}, %2;" : "=f"(lo), "=f"(hi) : "l"(v));
    return lo + hi;
}

// ---------------------------------------------------------------------------
// Prep: per-query norms, gate logits, softmax term weights; initialize d_out
// with the constant term  out_b + out_w * (w2*b1 + b2) * sum(tw).
// Grid: BB blocks x 512 threads (16 warps, one warp per query term).
// ---------------------------------------------------------------------------
__global__ void drmm_prep(const int* __restrict__ bq,
                          const float* __restrict__ emb,
                          const float* __restrict__ gate_w,
                          const float* __restrict__ gate_b,
                          const float* __restrict__ b1,
                          const float* __restrict__ w2,
                          const float* __restrict__ b2,
                          const float* __restrict__ out_w,
                          const float* __restrict__ out_b,
                          float* __restrict__ out) {
    const int b = blockIdx.x;
    const int lane = threadIdx.x & 31;
    const int q = threadIdx.x >> 5;

    __shared__ float s_logit[QQ];

    const int tok = bq[b * QQ + q];
    const float* row = emb + (long long)tok * EMS;
    float ssv = 0.f, gd = 0.f;
    for (int k = lane; k < EMS; k += 32) {
        float e = row[k];
        ssv = fmaf(e, e, ssv);
        gd = fmaf(e, gate_w[k], gd);
    }
#pragma unroll
    for (int o = 16; o > 0; o >>= 1) {
        ssv += __shfl_xor_sync(0xffffffffu, ssv, o);
        gd += __shfl_xor_sync(0xffffffffu, gd, o);
    }
    if (lane == 0) {
        g_nq[b * QQ + q] = sqrtf(ssv);
        s_logit[q] = gd + gate_b[0];
    }
    __syncthreads();

    if (threadIdx.x < 32) {
        float v = (lane < QQ) ? s_logit[lane] : -3.402823466e38f;
        float m = v;
#pragma unroll
        for (int o = 16; o > 0; o >>= 1)
            m = fmaxf(m, __shfl_xor_sync(0xffffffffu, m, o));
        float e = (lane < QQ) ? expf(v - m) : 0.f;
        float s = e;
#pragma unroll
        for (int o = 16; o > 0; o >>= 1)
            s += __shfl_xor_sync(0xffffffffu, s, o);
        float tw = e / s;
        if (lane < QQ) g_tw[b * QQ + lane] = tw;
        float st = (lane < QQ) ? tw : 0.f;
#pragma unroll
        for (int o = 16; o > 0; o >>= 1)
            st += __shfl_xor_sync(0xffffffffu, st, o);
        if (lane == 0) {
            float C = w2[0] * b1[0] + b2[0];
            float init = out_b[0] + out_w[0] * C * st;
            for (int d = 0; d < DD; ++d) out[b * DD + d] = init;
        }
    }
}

// ---------------------------------------------------------------------------
// Main: one block per (b,d,half-of-L). Warp layout: lane = lg*4 + kq.
// Each 4-lane group owns one l-slot; each lane covers one k-quarter (float4
// granularity) so doc-row global loads are 64B-contiguous per row. All 16
// query dots accumulate in registers as f32x2 pairs over k. Query tile in
// smem (broadcast reads). Doc sum-of-squares computed in the same loop.
// ---------------------------------------------------------------------------
__global__ __launch_bounds__(256, 2) void drmm_main(
    const int* __restrict__ bq, const int* __restrict__ docs,
    const float* __restrict__ emb, const float* __restrict__ w1,
    const float* __restrict__ w2, const float* __restrict__ out_w,
    float* __restrict__ out) {
    const int bd = blockIdx.x >> 1;
    const int half = blockIdx.x & 1;
    const int b_ = bd / DD;
    const int tid = threadIdx.x;
    const int lane = tid & 31;
    const int warp = tid >> 5;
    const int kq = lane & 3;
    const int slot = (warp << 3) + (lane >> 2);  // 0..63

    __shared__ __align__(16) float qs[QQ][304];  // 300 + pad (zeros)
    __shared__ float sphi[QQ];

    // Cooperative, coalesced load of the 16 query embeddings (+ zero pad).
    for (int i = tid; i < QQ * 76; i += 256) {
        int q = i / 76, c4 = i - q * 76;
        float4 v = make_float4(0.f, 0.f, 0.f, 0.f);
        if (c4 < 75) {
            int tok = bq[b_ * QQ + q];
            v = *reinterpret_cast<const float4*>(emb + (long long)tok * EMS + c4 * 4);
        }
        *reinterpret_cast<float4*>(&qs[q][c4 * 4]) = v;
    }
    if (tid < QQ) sphi[tid] = 0.f;

    float w1r[5];
#pragma unroll
    for (int i = 0; i < 5; ++i) w1r[i] = w1[i];
    float mynq[4];
#pragma unroll
    for (int j = 0; j < 4; ++j) mynq[j] = g_nq[b_ * QQ + kq * 4 + j];

    __syncthreads();

    float phi[4] = {0.f, 0.f, 0.f, 0.f};
    const int lbase = half * LCHUNK;
    const int iters = (LCHUNK + 63) >> 6;

    for (int it = 0; it < iters; ++it) {
        int l = lbase + slot + (it << 6);
        bool active = (l < lbase + LCHUNK);
        int lc = active ? l : (lbase + LCHUNK - 1);
        int tok = docs[bd * LL + lc];
        const float* drow = emb + (long long)tok * EMS;

        unsigned long long acc[QQ];
#pragma unroll
        for (int q = 0; q < QQ; ++q) acc[q] = 0ull;
        unsigned long long ss = 0ull;

        int k0 = kq << 2;
        ulonglong2 dv = *reinterpret_cast<const ulonglong2*>(drow + k0);
#pragma unroll
        for (int kc = 0; kc < 19; ++kc) {
            ulonglong2 dn = make_ulonglong2(0ull, 0ull);
            int kn = k0 + 16;
            if (kc < 18 && kn < EMS)
                dn = *reinterpret_cast<const ulonglong2*>(drow + kn);
            ss = fma2(dv.x, dv.x, ss);
            ss = fma2(dv.y, dv.y, ss);
#pragma unroll
            for (int q = 0; q < QQ; ++q) {
                ulonglong2 qv = *reinterpret_cast<const ulonglong2*>(&qs[q][k0]);
                acc[q] = fma2(qv.x, dv.x, acc[q]);
                acc[q] = fma2(qv.y, dv.y, acc[q]);
            }
            dv = dn;
            k0 = kn;
        }

        float dot[QQ];
#pragma unroll
        for (int q = 0; q < QQ; ++q) dot[q] = lo_plus_hi(acc[q]);
        float ssf = lo_plus_hi(ss);

        // Reduce over the 4 k-quarter lanes of this l-slot.
#pragma unroll
        for (int q = 0; q < QQ; ++q) {
            dot[q] += __shfl_xor_sync(0xffffffffu, dot[q], 1);
            dot[q] += __shfl_xor_sync(0xffffffffu, dot[q], 2);
        }
        ssf += __shfl_xor_sync(0xffffffffu, ssf, 1);
        ssf += __shfl_xor_sync(0xffffffffu, ssf, 2);

        if (active) {
            float nd = sqrtf(ssf);
#pragma unroll
            for (int j = 0; j < 4; ++j) {
                float c = dot[kq * 4 + j] / fmaxf(mynq[j] * nd, 1e-8f);
                // bins: [-1,-.5) [-.5,0) [0,.5) [.5,1) [1,1]; outside -> 0
                float p;
                if (c >= 0.5f)
                    p = (c < 1.0f) ? w1r[3] : ((c <= 1.0f) ? w1r[4] : 0.0f);
                else if (c >= 0.0f)
                    p = w1r[2];
                else if (c >= -0.5f)
                    p = w1r[1];
                else
                    p = (c >= -1.0f) ? w1r[0] : 0.0f;
                phi[j] += p;
            }
        }
    }

#pragma unroll
    for (int j = 0; j < 4; ++j) atomicAdd(&sphi[kq * 4 + j], phi[j]);
    __syncthreads();

    if (tid == 0) {
        float partial = 0.f;
#pragma unroll
        for (int q = 0; q < QQ; ++q) partial += g_tw[b_ * QQ + q] * sphi[q];
        atomicAdd(&out[bd], out_w[0] * w2[0] * partial);
    }
}

extern "C" void kernel_launch(void* const* d_in, const int* in_sizes, int n_in,
                              void* d_out, int out_size) {
    const int* bq = (const int*)d_in[0];
    const int* docs = (const int*)d_in[1];
    const float* emb = (const float*)d_in[2];
    const float* gate_w = (const float*)d_in[3];
    const float* gate_b = (const float*)d_in[4];
    const float* w1 = (const float*)d_in[5];
    const float* b1 = (const float*)d_in[6];
    const float* w2 = (const float*)d_in[7];
    const float* b2 = (const float*)d_in[8];
    const float* out_w = (const float*)d_in[9];
    const float* out_b = (const float*)d_in[10];
    float* out = (float*)d_out;

    drmm_prep<<<BB, 512>>>(bq, emb, gate_w, gate_b, b1, w2, b2, out_w, out_b, out);
    drmm_main<<<BB * DD * SPLIT, 256>>>(bq, docs, emb, w1, w2, out_w, out);
}

// round 3
// speedup vs baseline: 2.8284x; 2.8284x over previous
#include <cuda_runtime.h>
#include <cstdint>

#define VOCABN 50000
#define EMS    300
#define BB     32
#define QQ     16
#define DD     10
#define LL     1000
#define NSPLIT 4
#define LCHUNK (LL / NSPLIT)   // 250 rows per block

__device__ float g_nq[BB * QQ];
__device__ float g_tw[BB * QQ];

__device__ __forceinline__ unsigned long long fma2(unsigned long long a,
                                                   unsigned long long b,
                                                   unsigned long long c) {
    unsigned long long d;
    asm("fma.rn.f32x2 %0, %1, %2, %3;" : "=l"(d) : "l"(a), "l"(b), "l"(c));
    return d;
}

__device__ __forceinline__ float lo_plus_hi(unsigned long long v) {
    float lo, hi;
    asm("mov.b64 {%0, %1}, %2;" : "=f"(lo), "=f"(hi) : "l"(v));
    return lo + hi;
}

// ---------------------------------------------------------------------------
// Prep: query norms, gate softmax weights; init d_out with the constant term
// out_b + out_w*(w2*b1+b2)*sum(tw).  BB blocks x 512 threads.
// ---------------------------------------------------------------------------
__global__ void drmm_prep(const int* __restrict__ bq,
                          const float* __restrict__ emb,
                          const float* __restrict__ gate_w,
                          const float* __restrict__ gate_b,
                          const float* __restrict__ b1,
                          const float* __restrict__ w2,
                          const float* __restrict__ b2,
                          const float* __restrict__ out_w,
                          const float* __restrict__ out_b,
                          float* __restrict__ out) {
    const int b = blockIdx.x;
    const int lane = threadIdx.x & 31;
    const int q = threadIdx.x >> 5;

    __shared__ float s_logit[QQ];

    const int tok = bq[b * QQ + q];
    const float* row = emb + (long long)tok * EMS;
    float ssv = 0.f, gd = 0.f;
    for (int k = lane; k < EMS; k += 32) {
        float e = row[k];
        ssv = fmaf(e, e, ssv);
        gd = fmaf(e, gate_w[k], gd);
    }
#pragma unroll
    for (int o = 16; o > 0; o >>= 1) {
        ssv += __shfl_xor_sync(0xffffffffu, ssv, o);
        gd += __shfl_xor_sync(0xffffffffu, gd, o);
    }
    if (lane == 0) {
        g_nq[b * QQ + q] = sqrtf(ssv);
        s_logit[q] = gd + gate_b[0];
    }
    __syncthreads();

    if (threadIdx.x < 32) {
        float v = (lane < QQ) ? s_logit[lane] : -3.402823466e38f;
        float m = v;
#pragma unroll
        for (int o = 16; o > 0; o >>= 1)
            m = fmaxf(m, __shfl_xor_sync(0xffffffffu, m, o));
        float e = (lane < QQ) ? expf(v - m) : 0.f;
        float s = e;
#pragma unroll
        for (int o = 16; o > 0; o >>= 1)
            s += __shfl_xor_sync(0xffffffffu, s, o);
        float tw = e / s;
        if (lane < QQ) g_tw[b * QQ + lane] = tw;
        float st = (lane < QQ) ? tw : 0.f;
#pragma unroll
        for (int o = 16; o > 0; o >>= 1)
            st += __shfl_xor_sync(0xffffffffu, st, o);
        if (lane == 0) {
            float C = w2[0] * b1[0] + b2[0];
            float init = out_b[0] + out_w[0] * C * st;
            for (int d = 0; d < DD; ++d) out[b * DD + d] = init;
        }
    }
}

// Guarded 16B doc-chunk load: lane kq owns k = 4*kq + 16*kc (valid iff <= 296).
__device__ __forceinline__ ulonglong2 ldchunk(const float* __restrict__ drow,
                                              int k) {
    if (k <= EMS - 4)
        return *reinterpret_cast<const ulonglong2*>(drow + k);
    return make_ulonglong2(0ull, 0ull);
}

// ---------------------------------------------------------------------------
// Main: one block per (b,d,quarter-of-L). Warp = 8 l-slots x 4 k-quarter
// lanes; doc-row global loads are 64B-contiguous per row. 16 q accumulators
// as f32x2 over k. q processed in groups of 4 (bounded live registers),
// depth-2 LDG pipeline with static rotation (unroll 2).
// ---------------------------------------------------------------------------
__global__ __launch_bounds__(256, 2) void drmm_main(
    const int* __restrict__ bq, const int* __restrict__ docs,
    const float* __restrict__ emb, const float* __restrict__ w1,
    const float* __restrict__ w2, const float* __restrict__ out_w,
    float* __restrict__ out) {
    const int bd = blockIdx.x >> 2;
    const int quarter = blockIdx.x & 3;
    const int b_ = bd / DD;
    const int tid = threadIdx.x;
    const int lane = tid & 31;
    const int warp = tid >> 5;
    const int kq = lane & 3;
    const int slot = (warp << 3) + (lane >> 2);  // 0..63

    __shared__ __align__(16) float qs[QQ][304];  // 300 + zero pad
    __shared__ float sphi[QQ];

    // Cooperative, coalesced staging of the 16 query embeddings (+ zero pad).
    for (int i = tid; i < QQ * 76; i += 256) {
        int q = i / 76, c4 = i - q * 76;
        float4 v = make_float4(0.f, 0.f, 0.f, 0.f);
        if (c4 < 75) {
            int tok = bq[b_ * QQ + q];
            v = *reinterpret_cast<const float4*>(emb + (long long)tok * EMS + c4 * 4);
        }
        *reinterpret_cast<float4*>(&qs[q][c4 * 4]) = v;
    }
    if (tid < QQ) sphi[tid] = 0.f;

    float mynq[4];
#pragma unroll
    for (int j = 0; j < 4; ++j) mynq[j] = g_nq[b_ * QQ + kq * 4 + j];

    __syncthreads();

    float phi[4] = {0.f, 0.f, 0.f, 0.f};
    const int lbase = quarter * LCHUNK;
    const int lend = lbase + LCHUNK;

    for (int l0 = lbase; l0 < lend; l0 += 64) {
        const int l = l0 + slot;
        const bool active = (l < lend);
        const int lc = active ? l : (lend - 1);
        const int tok = __ldg(&docs[bd * LL + lc]);
        const float* drow = emb + (long long)tok * EMS;

        unsigned long long acc[QQ];
#pragma unroll
        for (int q = 0; q < QQ; ++q) acc[q] = 0ull;
        unsigned long long ss = 0ull;

        const int kbase = kq << 2;
        // depth-2 software pipeline over the 19 k-chunks
        ulonglong2 cur = ldchunk(drow, kbase);
        ulonglong2 nxt = ldchunk(drow, kbase + 16);

#pragma unroll 2
        for (int kc = 0; kc < 19; ++kc) {
            const int k0 = kbase + kc * 16;
            ulonglong2 dv = cur;
            cur = nxt;
            nxt = ldchunk(drow, k0 + 32);

            ss = fma2(dv.x, dv.x, ss);
            ss = fma2(dv.y, dv.y, ss);
#pragma unroll
            for (int g = 0; g < 4; ++g) {
#pragma unroll
                for (int j = 0; j < 4; ++j) {
                    const int q = g * 4 + j;
                    ulonglong2 qv =
                        *reinterpret_cast<const ulonglong2*>(&qs[q][k0]);
                    acc[q] = fma2(qv.x, dv.x, acc[q]);
                    acc[q] = fma2(qv.y, dv.y, acc[q]);
                }
            }
        }

        // Collapse f32x2 pairs, then reduce over the 4 k-quarter lanes.
        float dsum[QQ];
#pragma unroll
        for (int q = 0; q < QQ; ++q) {
            float v = lo_plus_hi(acc[q]);
            v += __shfl_xor_sync(0xffffffffu, v, 1);
            v += __shfl_xor_sync(0xffffffffu, v, 2);
            dsum[q] = v;
        }
        float ssf = lo_plus_hi(ss);
        ssf += __shfl_xor_sync(0xffffffffu, ssf, 1);
        ssf += __shfl_xor_sync(0xffffffffu, ssf, 2);

        if (active) {
            const float nd = sqrtf(ssf);
#pragma unroll
            for (int j = 0; j < 4; ++j) {
                float c = dsum[kq * 4 + j] / fmaxf(mynq[j] * nd, 1e-8f);
                // bins: [-1,-.5) [-.5,0) [0,.5) [.5,1) [1,1]; outside -> 0
                float p;
                if (c >= 0.5f)
                    p = (c < 1.0f) ? w1[3] : ((c <= 1.0f) ? w1[4] : 0.0f);
                else if (c >= 0.0f)
                    p = w1[2];
                else if (c >= -0.5f)
                    p = w1[1];
                else
                    p = (c >= -1.0f) ? w1[0] : 0.0f;
                phi[j] += p;
            }
        }
    }

#pragma unroll
    for (int j = 0; j < 4; ++j) atomicAdd(&sphi[kq * 4 + j], phi[j]);
    __syncthreads();

    if (tid == 0) {
        float partial = 0.f;
#pragma unroll
        for (int q = 0; q < QQ; ++q) partial += g_tw[b_ * QQ + q] * sphi[q];
        atomicAdd(&out[bd], out_w[0] * w2[0] * partial);
    }
}

extern "C" void kernel_launch(void* const* d_in, const int* in_sizes, int n_in,
                              void* d_out, int out_size) {
    const int* bq = (const int*)d_in[0];
    const int* docs = (const int*)d_in[1];
    const float* emb = (const float*)d_in[2];
    const float* gate_w = (const float*)d_in[3];
    const float* gate_b = (const float*)d_in[4];
    const float* w1 = (const float*)d_in[5];
    const float* b1 = (const float*)d_in[6];
    const float* w2 = (const float*)d_in[7];
    const float* b2 = (const float*)d_in[8];
    const float* out_w = (const float*)d_in[9];
    const float* out_b = (const float*)d_in[10];
    float* out = (float*)d_out;

    drmm_prep<<<BB, 512>>>(bq, emb, gate_w, gate_b, b1, w2, b2, out_w, out_b, out);
    drmm_main<<<BB * DD * NSPLIT, 256>>>(bq, docs, emb, w1, w2, out_w, out);
}

// round 8
// speedup vs baseline: 5.8523x; 2.0691x over previous
#include <cuda_runtime.h>
#include <cstdint>

#define VOCABN 50000
#define EMS    300
#define BB     32
#define QQ     16
#define DD     10
#define LL     1000
#define NSPLIT 4
#define LCHUNK (LL / NSPLIT)   // 250 rows per block

__device__ float g_nq[BB * QQ];
__device__ float g_tw[BB * QQ];

__device__ __forceinline__ unsigned long long fma2(unsigned long long a,
                                                   unsigned long long b,
                                                   unsigned long long c) {
    unsigned long long d;
    asm("fma.rn.f32x2 %0, %1, %2, %3;" : "=l"(d) : "l"(a), "l"(b), "l"(c));
    return d;
}

__device__ __forceinline__ float lo_plus_hi(unsigned long long v) {
    float lo, hi;
    asm("mov.b64 {%0, %1}, %2;" : "=f"(lo), "=f"(hi) : "l"(v));
    return lo + hi;
}

// ---------------------------------------------------------------------------
// Prep: query norms, gate softmax weights; init d_out with the constant term
// out_b + out_w*(w2*b1+b2)*sum(tw).  BB blocks x 512 threads.
// ---------------------------------------------------------------------------
__global__ void drmm_prep(const int* __restrict__ bq,
                          const float* __restrict__ emb,
                          const float* __restrict__ gate_w,
                          const float* __restrict__ gate_b,
                          const float* __restrict__ b1,
                          const float* __restrict__ w2,
                          const float* __restrict__ b2,
                          const float* __restrict__ out_w,
                          const float* __restrict__ out_b,
                          float* __restrict__ out) {
    const int b = blockIdx.x;
    const int lane = threadIdx.x & 31;
    const int q = threadIdx.x >> 5;

    __shared__ float s_logit[QQ];

    const int tok = bq[b * QQ + q];
    const float* row = emb + (long long)tok * EMS;
    float ssv = 0.f, gd = 0.f;
    for (int k = lane; k < EMS; k += 32) {
        float e = row[k];
        ssv = fmaf(e, e, ssv);
        gd = fmaf(e, gate_w[k], gd);
    }
#pragma unroll
    for (int o = 16; o > 0; o >>= 1) {
        ssv += __shfl_xor_sync(0xffffffffu, ssv, o);
        gd += __shfl_xor_sync(0xffffffffu, gd, o);
    }
    if (lane == 0) {
        g_nq[b * QQ + q] = sqrtf(ssv);
        s_logit[q] = gd + gate_b[0];
    }
    __syncthreads();

    if (threadIdx.x < 32) {
        float v = (lane < QQ) ? s_logit[lane] : -3.402823466e38f;
        float m = v;
#pragma unroll
        for (int o = 16; o > 0; o >>= 1)
            m = fmaxf(m, __shfl_xor_sync(0xffffffffu, m, o));
        float e = (lane < QQ) ? expf(v - m) : 0.f;
        float s = e;
#pragma unroll
        for (int o = 16; o > 0; o >>= 1)
            s += __shfl_xor_sync(0xffffffffu, s, o);
        float tw = e / s;
        if (lane < QQ) g_tw[b * QQ + lane] = tw;
        float st = (lane < QQ) ? tw : 0.f;
#pragma unroll
        for (int o = 16; o > 0; o >>= 1)
            st += __shfl_xor_sync(0xffffffffu, st, o);
        if (lane == 0) {
            float C = w2[0] * b1[0] + b2[0];
            float init = out_b[0] + out_w[0] * C * st;
            for (int d = 0; d < DD; ++d) out[b * DD + d] = init;
        }
    }
}

// Guarded 16B doc-chunk load: lane kq owns k = 4*kq + 16*kc (valid iff <= 296).
__device__ __forceinline__ ulonglong2 ldchunk(const float* __restrict__ drow,
                                              int k) {
    if (k <= EMS - 4)
        return *reinterpret_cast<const ulonglong2*>(drow + k);
    return make_ulonglong2(0ull, 0ull);
}

__device__ __forceinline__ float binw(float v, float nd, float h,
                                      const float* __restrict__ w1r) {
    // bins: [-1,-.5) [-.5,0) [0,.5) [.5,1) [1,1]; outside -> 0
    if (v >= h) return (v < nd) ? w1r[3] : ((v <= nd) ? w1r[4] : 0.0f);
    if (v >= 0.0f) return w1r[2];
    if (v >= -h) return w1r[1];
    return (v >= -nd) ? w1r[0] : 0.0f;
}

// ---------------------------------------------------------------------------
// Main: one block per (b,d,quarter-of-L). Warp = 8 l-groups x 4 k-quarter
// lanes; each group owns TWO doc rows (slot, slot+64) so every smem q-vector
// load feeds FMAs for both rows (LDS per FMA halved). Query tile in smem is
// pre-scaled by 1/||q|| so binning compares dot against +-nd thresholds with
// no division. 32 f32x2 accumulators, depth-2 LDG pipeline per row; the
// chunk loop stays rolled (small I-footprint, pipeline gives the MLP).
// ---------------------------------------------------------------------------
__global__ __launch_bounds__(256, 2) void drmm_main(
    const int* __restrict__ bq, const int* __restrict__ docs,
    const float* __restrict__ emb, const float* __restrict__ w1,
    const float* __restrict__ w2, const float* __restrict__ out_w,
    float* __restrict__ out) {
    const int bd = blockIdx.x >> 2;
    const int quarter = blockIdx.x & 3;
    const int b_ = bd / DD;
    const int tid = threadIdx.x;
    const int lane = tid & 31;
    const int warp = tid >> 5;
    const int kq = lane & 3;
    const int slot = (warp << 3) + (lane >> 2);  // 0..63

    __shared__ __align__(16) float qs[QQ][304];  // q-hat (q/||q||), zero pad
    __shared__ float sphi[QQ];

    // Cooperative staging of the 16 query embeddings, scaled by 1/||q||.
    for (int i = tid; i < QQ * 76; i += 256) {
        int q = i / 76, c4 = i - q * 76;
        float4 v = make_float4(0.f, 0.f, 0.f, 0.f);
        if (c4 < 75) {
            int tok = bq[b_ * QQ + q];
            float rnq = 1.0f / g_nq[b_ * QQ + q];
            v = *reinterpret_cast<const float4*>(emb + (long long)tok * EMS + c4 * 4);
            v.x *= rnq; v.y *= rnq; v.z *= rnq; v.w *= rnq;
        }
        *reinterpret_cast<float4*>(&qs[q][c4 * 4]) = v;
    }
    if (tid < QQ) sphi[tid] = 0.f;

    float w1r[5];
#pragma unroll
    for (int i = 0; i < 5; ++i) w1r[i] = w1[i];

    __syncthreads();

    float phi[4] = {0.f, 0.f, 0.f, 0.f};
    const int lbase = quarter * LCHUNK;
    const int lend = lbase + LCHUNK;

    for (int l0 = lbase; l0 < lend; l0 += 128) {
        const int la = l0 + slot;
        const int lb = la + 64;
        const bool act0 = (la < lend);
        const bool act1 = (lb < lend);
        const int tok0 = __ldg(&docs[bd * LL + (act0 ? la : lend - 1)]);
        const int tok1 = __ldg(&docs[bd * LL + (act1 ? lb : lend - 1)]);
        const float* row0 = emb + (long long)tok0 * EMS;
        const float* row1 = emb + (long long)tok1 * EMS;

        unsigned long long acc0[QQ], acc1[QQ];
#pragma unroll
        for (int q = 0; q < QQ; ++q) { acc0[q] = 0ull; acc1[q] = 0ull; }
        unsigned long long ss0 = 0ull, ss1 = 0ull;

        const int kbase = kq << 2;
        ulonglong2 cur0 = ldchunk(row0, kbase);
        ulonglong2 cur1 = ldchunk(row1, kbase);
        ulonglong2 nxt0 = ldchunk(row0, kbase + 16);
        ulonglong2 nxt1 = ldchunk(row1, kbase + 16);

#pragma unroll 1
        for (int kc = 0; kc < 19; ++kc) {
            const int k0 = kbase + kc * 16;
            ulonglong2 dv0 = cur0, dv1 = cur1;
            cur0 = nxt0; cur1 = nxt1;
            nxt0 = ldchunk(row0, k0 + 32);
            nxt1 = ldchunk(row1, k0 + 32);

            ss0 = fma2(dv0.x, dv0.x, ss0);
            ss0 = fma2(dv0.y, dv0.y, ss0);
            ss1 = fma2(dv1.x, dv1.x, ss1);
            ss1 = fma2(dv1.y, dv1.y, ss1);
#pragma unroll
            for (int q = 0; q < QQ; ++q) {
                ulonglong2 qv = *reinterpret_cast<const ulonglong2*>(&qs[q][k0]);
                acc0[q] = fma2(qv.x, dv0.x, acc0[q]);
                acc0[q] = fma2(qv.y, dv0.y, acc0[q]);
                acc1[q] = fma2(qv.x, dv1.x, acc1[q]);
                acc1[q] = fma2(qv.y, dv1.y, acc1[q]);
            }
        }

        // Collapse f32x2 pairs, reduce over the 4 k-quarter lanes, and bin by
        // comparing dot against nd-scaled thresholds (no division).
        float ssf0 = lo_plus_hi(ss0), ssf1 = lo_plus_hi(ss1);
        ssf0 += __shfl_xor_sync(0xffffffffu, ssf0, 1);
        ssf0 += __shfl_xor_sync(0xffffffffu, ssf0, 2);
        ssf1 += __shfl_xor_sync(0xffffffffu, ssf1, 1);
        ssf1 += __shfl_xor_sync(0xffffffffu, ssf1, 2);
        const float nd0 = sqrtf(ssf0);
        const float nd1 = sqrtf(ssf1);
        const float h0 = 0.5f * nd0, h1 = 0.5f * nd1;

#pragma unroll
        for (int q = 0; q < QQ; ++q) {
            float v0 = lo_plus_hi(acc0[q]);
            float v1 = lo_plus_hi(acc1[q]);
            v0 += __shfl_xor_sync(0xffffffffu, v0, 1);
            v0 += __shfl_xor_sync(0xffffffffu, v0, 2);
            v1 += __shfl_xor_sync(0xffffffffu, v1, 1);
            v1 += __shfl_xor_sync(0xffffffffu, v1, 2);
            if ((q >> 2) == kq) {
                const int j = q & 3;
                if (act0) phi[j] += binw(v0, nd0, h0, w1r);
                if (act1) phi[j] += binw(v1, nd1, h1, w1r);
            }
        }
    }

#pragma unroll
    for (int j = 0; j < 4; ++j) atomicAdd(&sphi[kq * 4 + j], phi[j]);
    __syncthreads();

    if (tid == 0) {
        float partial = 0.f;
#pragma unroll
        for (int q = 0; q < QQ; ++q) partial += g_tw[b_ * QQ + q] * sphi[q];
        atomicAdd(&out[bd], out_w[0] * w2[0] * partial);
    }
}

extern "C" void kernel_launch(void* const* d_in, const int* in_sizes, int n_in,
                              void* d_out, int out_size) {
    const int* bq = (const int*)d_in[0];
    const int* docs = (const int*)d_in[1];
    const float* emb = (const float*)d_in[2];
    const float* gate_w = (const float*)d_in[3];
    const float* gate_b = (const float*)d_in[4];
    const float* w1 = (const float*)d_in[5];
    const float* b1 = (const float*)d_in[6];
    const float* w2 = (const float*)d_in[7];
    const float* b2 = (const float*)d_in[8];
    const float* out_w = (const float*)d_in[9];
    const float* out_b = (const float*)d_in[10];
    float* out = (float*)d_out;

    drmm_prep<<<BB, 512>>>(bq, emb, gate_w, gate_b, b1, w2, b2, out_w, out_b, out);
    drmm_main<<<BB * DD * NSPLIT, 256>>>(bq, docs, emb, w1, w2, out_w, out);
}

// round 12
// speedup vs baseline: 6.7963x; 1.1613x over previous
#include <cuda_runtime.h>
#include <cstdint>

#define VOCABN 50000
#define EMS    300
#define BB     32
#define QQ     16
#define DD     10
#define LL     1000
#define NSPLIT 4
#define LCHUNK (LL / NSPLIT)   // 250 rows per block

__device__ float g_nq[BB * QQ];
__device__ float g_tw[BB * QQ];

__device__ __forceinline__ unsigned long long fma2(unsigned long long a,
                                                   unsigned long long b,
                                                   unsigned long long c) {
    unsigned long long d;
    asm("fma.rn.f32x2 %0, %1, %2, %3;" : "=l"(d) : "l"(a), "l"(b), "l"(c));
    return d;
}

__device__ __forceinline__ float lo_plus_hi(unsigned long long v) {
    float lo, hi;
    asm("mov.b64 {%0, %1}, %2;" : "=f"(lo), "=f"(hi) : "l"(v));
    return lo + hi;
}

// ---------------------------------------------------------------------------
// Prep: query norms, gate softmax weights; init d_out with the constant term
// out_b + out_w*(w2*b1+b2)*sum(tw).  BB blocks x 512 threads.
// ---------------------------------------------------------------------------
__global__ void drmm_prep(const int* __restrict__ bq,
                          const float* __restrict__ emb,
                          const float* __restrict__ gate_w,
                          const float* __restrict__ gate_b,
                          const float* __restrict__ b1,
                          const float* __restrict__ w2,
                          const float* __restrict__ b2,
                          const float* __restrict__ out_w,
                          const float* __restrict__ out_b,
                          float* __restrict__ out) {
    const int b = blockIdx.x;
    const int lane = threadIdx.x & 31;
    const int q = threadIdx.x >> 5;

    __shared__ float s_logit[QQ];

    const int tok = bq[b * QQ + q];
    const float* row = emb + (long long)tok * EMS;
    float ssv = 0.f, gd = 0.f;
    for (int k = lane; k < EMS; k += 32) {
        float e = row[k];
        ssv = fmaf(e, e, ssv);
        gd = fmaf(e, gate_w[k], gd);
    }
#pragma unroll
    for (int o = 16; o > 0; o >>= 1) {
        ssv += __shfl_xor_sync(0xffffffffu, ssv, o);
        gd += __shfl_xor_sync(0xffffffffu, gd, o);
    }
    if (lane == 0) {
        g_nq[b * QQ + q] = sqrtf(ssv);
        s_logit[q] = gd + gate_b[0];
    }
    __syncthreads();

    if (threadIdx.x < 32) {
        float v = (lane < QQ) ? s_logit[lane] : -3.402823466e38f;
        float m = v;
#pragma unroll
        for (int o = 16; o > 0; o >>= 1)
            m = fmaxf(m, __shfl_xor_sync(0xffffffffu, m, o));
        float e = (lane < QQ) ? expf(v - m) : 0.f;
        float s = e;
#pragma unroll
        for (int o = 16; o > 0; o >>= 1)
            s += __shfl_xor_sync(0xffffffffu, s, o);
        float tw = e / s;
        if (lane < QQ) g_tw[b * QQ + lane] = tw;
        float st = (lane < QQ) ? tw : 0.f;
#pragma unroll
        for (int o = 16; o > 0; o >>= 1)
            st += __shfl_xor_sync(0xffffffffu, st, o);
        if (lane == 0) {
            float C = w2[0] * b1[0] + b2[0];
            float init = out_b[0] + out_w[0] * C * st;
            for (int d = 0; d < DD; ++d) out[b * DD + d] = init;
        }
    }
}

// Guarded 16B doc-chunk load: valid iff k <= 296 (floats k..k+3 within 300).
__device__ __forceinline__ ulonglong2 ldchunk(const float* __restrict__ drow,
                                              int k) {
    if (k <= EMS - 4)
        return *reinterpret_cast<const ulonglong2*>(drow + k);
    return make_ulonglong2(0ull, 0ull);
}

__device__ __forceinline__ float binw(float v, float nd, float h,
                                      const float* __restrict__ w1r) {
    // bins: [-1,-.5) [-.5,0) [0,.5) [.5,1) [1,1]; outside -> 0
    if (v >= h) return (v < nd) ? w1r[3] : ((v <= nd) ? w1r[4] : 0.0f);
    if (v >= 0.0f) return w1r[2];
    if (v >= -h) return w1r[1];
    return (v >= -nd) ? w1r[0] : 0.0f;
}

// Split-butterfly reduce of v[16] across an aligned 8-lane group.
// On return, v[0], v[1] hold the full sums for q = 2*kp, 2*kp+1.
__device__ __forceinline__ void reduce16_8(float* v, int kp) {
    {
        const bool hi = (kp & 4) != 0;
#pragma unroll
        for (int i = 0; i < 8; ++i) {
            float give = hi ? v[i] : v[8 + i];
            float got = __shfl_xor_sync(0xffffffffu, give, 4);
            v[i] = (hi ? v[8 + i] : v[i]) + got;
        }
    }
    {
        const bool hi = (kp & 2) != 0;
#pragma unroll
        for (int i = 0; i < 4; ++i) {
            float give = hi ? v[i] : v[4 + i];
            float got = __shfl_xor_sync(0xffffffffu, give, 2);
            v[i] = (hi ? v[4 + i] : v[i]) + got;
        }
    }
    {
        const bool hi = (kp & 1) != 0;
#pragma unroll
        for (int i = 0; i < 2; ++i) {
            float give = hi ? v[i] : v[2 + i];
            float got = __shfl_xor_sync(0xffffffffu, give, 1);
            v[i] = (hi ? v[2 + i] : v[i]) + got;
        }
    }
}

// ---------------------------------------------------------------------------
// Main: one block per (b,d,quarter-of-L). Warp = 4 groups x 8 lanes; each
// group owns TWO doc rows (slot, slot+32). Each lane loads 16B per chunk so
// a group's row access is 128B contiguous (warp LDG touches only 4 rows ->
// half the L1 wavefronts of the 4-lane layout). Every q-vector LDS is 128B
// (8 distinct addrs) and feeds FMAs for both rows. Query tile pre-scaled by
// 1/||q||; binning compares dot against +-nd (no division). Split-butterfly
// reduction leaves each lane owning 2 q's (14 shfl per row instead of 48).
// ---------------------------------------------------------------------------
__global__ __launch_bounds__(256, 2) void drmm_main(
    const int* __restrict__ bq, const int* __restrict__ docs,
    const float* __restrict__ emb, const float* __restrict__ w1,
    const float* __restrict__ w2, const float* __restrict__ out_w,
    float* __restrict__ out) {
    const int bd = blockIdx.x >> 2;
    const int quarter = blockIdx.x & 3;
    const int b_ = bd / DD;
    const int tid = threadIdx.x;
    const int lane = tid & 31;
    const int warp = tid >> 5;
    const int kp = lane & 7;                  // k-position within group
    const int slot = (warp << 2) + (lane >> 3);  // 0..31
    const int kp4 = kp << 2;

    __shared__ __align__(16) float qs[QQ][320];  // q-hat, zero pad to 320
    __shared__ float sphi[QQ];

    // Cooperative staging of the 16 query embeddings, scaled by 1/||q||.
    for (int i = tid; i < QQ * 80; i += 256) {
        int q = i / 80, c4 = i - q * 80;
        float4 v = make_float4(0.f, 0.f, 0.f, 0.f);
        if (c4 < 75) {
            int tok = bq[b_ * QQ + q];
            float rnq = 1.0f / g_nq[b_ * QQ + q];
            v = *reinterpret_cast<const float4*>(emb + (long long)tok * EMS + c4 * 4);
            v.x *= rnq; v.y *= rnq; v.z *= rnq; v.w *= rnq;
        }
        *reinterpret_cast<float4*>(&qs[q][c4 * 4]) = v;
    }
    if (tid < QQ) sphi[tid] = 0.f;

    float w1r[5];
#pragma unroll
    for (int i = 0; i < 5; ++i) w1r[i] = w1[i];

    __syncthreads();

    float phi[2] = {0.f, 0.f};  // this lane's q = 2*kp, 2*kp+1
    const int lbase = quarter * LCHUNK;
    const int lend = lbase + LCHUNK;

    for (int l0 = lbase; l0 < lend; l0 += 64) {
        const int la = l0 + slot;
        const int lb = la + 32;
        const bool act0 = (la < lend);
        const bool act1 = (lb < lend);
        const int tok0 = __ldg(&docs[bd * LL + (act0 ? la : lend - 1)]);
        const int tok1 = __ldg(&docs[bd * LL + (act1 ? lb : lend - 1)]);
        const float* row0 = emb + (long long)tok0 * EMS;
        const float* row1 = emb + (long long)tok1 * EMS;

        unsigned long long acc0[QQ], acc1[QQ];
#pragma unroll
        for (int q = 0; q < QQ; ++q) { acc0[q] = 0ull; acc1[q] = 0ull; }
        unsigned long long ss0 = 0ull, ss1 = 0ull;

        // depth-2 LDG pipeline over the 10 k-chunks (32 floats per chunk)
        ulonglong2 cur0 = ldchunk(row0, kp4);
        ulonglong2 cur1 = ldchunk(row1, kp4);
        ulonglong2 nxt0 = ldchunk(row0, kp4 + 32);
        ulonglong2 nxt1 = ldchunk(row1, kp4 + 32);

#pragma unroll 1
        for (int c = 0; c < 10; ++c) {
            const int k0 = kp4 + c * 32;
            ulonglong2 dv0 = cur0, dv1 = cur1;
            cur0 = nxt0; cur1 = nxt1;
            nxt0 = ldchunk(row0, k0 + 64);
            nxt1 = ldchunk(row1, k0 + 64);

            ss0 = fma2(dv0.x, dv0.x, ss0);
            ss0 = fma2(dv0.y, dv0.y, ss0);
            ss1 = fma2(dv1.x, dv1.x, ss1);
            ss1 = fma2(dv1.y, dv1.y, ss1);
#pragma unroll
            for (int q = 0; q < QQ; ++q) {
                ulonglong2 qv = *reinterpret_cast<const ulonglong2*>(&qs[q][k0]);
                acc0[q] = fma2(qv.x, dv0.x, acc0[q]);
                acc0[q] = fma2(qv.y, dv0.y, acc0[q]);
                acc1[q] = fma2(qv.x, dv1.x, acc1[q]);
                acc1[q] = fma2(qv.y, dv1.y, acc1[q]);
            }
        }

        // Doc norms: full butterfly over the 8-lane group.
        float ssf0 = lo_plus_hi(ss0), ssf1 = lo_plus_hi(ss1);
#pragma unroll
        for (int o = 1; o < 8; o <<= 1) {
            ssf0 += __shfl_xor_sync(0xffffffffu, ssf0, o);
            ssf1 += __shfl_xor_sync(0xffffffffu, ssf1, o);
        }
        const float nd0 = sqrtf(ssf0);
        const float nd1 = sqrtf(ssf1);
        const float h0 = 0.5f * nd0, h1 = 0.5f * nd1;

        // Split-butterfly: each lane ends owning q = 2*kp, 2*kp+1.
        float v0[QQ], v1[QQ];
#pragma unroll
        for (int q = 0; q < QQ; ++q) {
            v0[q] = lo_plus_hi(acc0[q]);
            v1[q] = lo_plus_hi(acc1[q]);
        }
        reduce16_8(v0, kp);
        reduce16_8(v1, kp);

        if (act0) {
            phi[0] += binw(v0[0], nd0, h0, w1r);
            phi[1] += binw(v0[1], nd0, h0, w1r);
        }
        if (act1) {
            phi[0] += binw(v1[0], nd1, h1, w1r);
            phi[1] += binw(v1[1], nd1, h1, w1r);
        }
    }

    atomicAdd(&sphi[2 * kp], phi[0]);
    atomicAdd(&sphi[2 * kp + 1], phi[1]);
    __syncthreads();

    if (tid == 0) {
        float partial = 0.f;
#pragma unroll
        for (int q = 0; q < QQ; ++q) partial += g_tw[b_ * QQ + q] * sphi[q];
        atomicAdd(&out[bd], out_w[0] * w2[0] * partial);
    }
}

extern "C" void kernel_launch(void* const* d_in, const int* in_sizes, int n_in,
                              void* d_out, int out_size) {
    const int* bq = (const int*)d_in[0];
    const int* docs = (const int*)d_in[1];
    const float* emb = (const float*)d_in[2];
    const float* gate_w = (const float*)d_in[3];
    const float* gate_b = (const float*)d_in[4];
    const float* w1 = (const float*)d_in[5];
    const float* b1 = (const float*)d_in[6];
    const float* w2 = (const float*)d_in[7];
    const float* b2 = (const float*)d_in[8];
    const float* out_w = (const float*)d_in[9];
    const float* out_b = (const float*)d_in[10];
    float* out = (float*)d_out;

    drmm_prep<<<BB, 512>>>(bq, emb, gate_w, gate_b, b1, w2, b2, out_w, out_b, out);
    drmm_main<<<BB * DD * NSPLIT, 256>>>(bq, docs, emb, w1, w2, out_w, out);
}